// round 12
// baseline (speedup 1.0000x reference)
#include <cuda_runtime.h>
#include <cstdint>

#define NQ      4096
#define NDB     65536
#define DIM     32
#define DAUX    32
#define KNN     5
#define NSLAB   (NDB / 8)          // 8192 8-point slabs
#define NSPLIT  2                  // db halves per query tile
#define QPC     64                 // queries per CTA (4 m-tiles)
#define NS      2048               // slabs per warp (quarter db)
#define BIGF    3.0e38f

// ---------------- global scratch ----------------
// g_Bf: frag-packed db tiles. Per slab s (8 points): 128 float4 =
//   [term hi|lo][i2 0|1][lane 0..31] ; lane's float4 = B[k=tig+4*(4*i2+c)][p=s*8+lane>>2]
__device__ float4 g_Bf[NSLAB * 128];          // 16 MB
__device__ float  g_hs[NDB];                  // 0.5*||db||^2
__device__ float  g_cs[NQ * 4 * KNN];         // 4 candidate lists of 5 per query
__device__ int    g_ci[NQ * 4 * KNN];

// ---------------- helpers ----------------
__device__ __forceinline__ float tf32r(float x) {
    uint32_t r;
    asm("cvt.rna.tf32.f32 %0, %1;" : "=r"(r) : "f"(x));
    return __uint_as_float(r);
}
__device__ __forceinline__ void mma8(float* c, const uint32_t* a,
                                     uint32_t b0, uint32_t b1) {
    asm("mma.sync.aligned.m16n8k8.row.col.f32.tf32.tf32.f32 "
        "{%0,%1,%2,%3}, {%4,%5,%6,%7}, {%8,%9}, {%0,%1,%2,%3};"
        : "+f"(c[0]), "+f"(c[1]), "+f"(c[2]), "+f"(c[3])
        : "r"(a[0]), "r"(a[1]), "r"(a[2]), "r"(a[3]), "r"(b0), "r"(b1));
}
__device__ __forceinline__ void topk_ins(float* ts, int* ti, float s, int pi) {
    if (s < ts[4]) {
        ts[4] = s; ti[4] = pi;
        if (ts[4] < ts[3]) { float f = ts[3]; ts[3] = ts[4]; ts[4] = f; int i = ti[3]; ti[3] = ti[4]; ti[4] = i; }
        if (ts[3] < ts[2]) { float f = ts[2]; ts[2] = ts[3]; ts[3] = f; int i = ti[2]; ti[2] = ti[3]; ti[3] = i; }
        if (ts[2] < ts[1]) { float f = ts[1]; ts[1] = ts[2]; ts[2] = f; int i = ti[1]; ti[1] = ti[2]; ti[2] = i; }
        if (ts[1] < ts[0]) { float f = ts[0]; ts[0] = ts[1]; ts[1] = f; int i = ti[0]; ti[0] = ti[1]; ti[1] = i; }
    }
}

// ---------------------------------------------------------------------------
// prep_hs: 0.5*||db||^2 per point. 8 lanes per point, coalesced float4 reads.
// ---------------------------------------------------------------------------
__global__ void prep_hs(const float* __restrict__ db) {
    const unsigned FULL = 0xffffffffu;
    const int p = blockIdx.x * 32 + (threadIdx.x >> 3);
    const int j = threadIdx.x & 7;
    float4 v = *(const float4*)(db + p * DIM + j * 4);
    float s = v.x * v.x + v.y * v.y + v.z * v.z + v.w * v.w;
    s += __shfl_xor_sync(FULL, s, 4, 8);
    s += __shfl_xor_sync(FULL, s, 2, 8);
    s += __shfl_xor_sync(FULL, s, 1, 8);
    if (j == 0) g_hs[p] = 0.5f * s;
}

// ---------------------------------------------------------------------------
// prep_bf: build frag-packed hi/lo db images.
// thread -> (slab s, i2, lane); writes one hi float4 and one lo float4.
// ---------------------------------------------------------------------------
__global__ void prep_bf(const float* __restrict__ db) {
    const int gid  = blockIdx.x * 256 + threadIdx.x;   // 0 .. 8192*64-1
    const int s    = gid >> 6;
    const int r    = gid & 63;
    const int i2   = r >> 5;
    const int lane = r & 31;
    const int tig  = lane & 3;
    const int p    = s * 8 + (lane >> 2);

    float hv[4], lv[4];
#pragma unroll
    for (int c = 0; c < 4; ++c) {
        int k = tig + 4 * (i2 * 4 + c);
        float v = db[p * DIM + k];
        float h = tf32r(v);
        hv[c] = h;
        lv[c] = tf32r(v - h);
    }
    g_Bf[s * 128 +      i2 * 32 + lane] = make_float4(hv[0], hv[1], hv[2], hv[3]);
    g_Bf[s * 128 + 64 + i2 * 32 + lane] = make_float4(lv[0], lv[1], lv[2], lv[3]);
}

// ---------------------------------------------------------------------------
// main: 128 CTAs (64 q-tiles x 2 db-splits), 256 threads (4 m-warps x 2 p-warps).
// A (queries, tf32 hi/lo) resident in registers; B streamed as packed frags
// via coalesced LDG.128; 12 chained tf32 HMMAs per 8-point slab; topk fused.
// ---------------------------------------------------------------------------
__global__ void __launch_bounds__(256, 1)
knn_mma(const float* __restrict__ q) {
    const unsigned FULL = 0xffffffffu;
    const int tid  = threadIdx.x;
    const int lane = tid & 31;
    const int tig  = lane & 3;
    const int wid  = tid >> 5;
    const int mi   = wid & 3;              // m-tile within CTA (16 queries)
    const int ph   = wid >> 2;             // p-half within this CTA's db split
    const int qb   = blockIdx.x >> 1;      // 0..63 query tile
    const int sp   = blockIdx.x & 1;       // db split
    const int w4   = sp * 2 + ph;          // candidate-list slot 0..3

    const int r0 = qb * QPC + mi * 16 + (lane >> 2);  // this thread's 2 queries
    const int r1 = r0 + 8;

    // ---- load A fragments (hi/lo), resident for the whole kernel ----
    uint32_t Ahi[4][4], Alo[4][4];
    {
        const float* q0 = q + r0 * DIM;
        const float* q1 = q + r1 * DIM;
#pragma unroll
        for (int ks = 0; ks < 4; ++ks) {
            int k0 = 8 * ks + tig;
            float v0 = q0[k0], v1 = q1[k0], v2 = q0[k0 + 4], v3 = q1[k0 + 4];
            float h0 = tf32r(v0), h1 = tf32r(v1), h2 = tf32r(v2), h3 = tf32r(v3);
            Ahi[ks][0] = __float_as_uint(h0);
            Ahi[ks][1] = __float_as_uint(h1);
            Ahi[ks][2] = __float_as_uint(h2);
            Ahi[ks][3] = __float_as_uint(h3);
            Alo[ks][0] = __float_as_uint(tf32r(v0 - h0));
            Alo[ks][1] = __float_as_uint(tf32r(v1 - h1));
            Alo[ks][2] = __float_as_uint(tf32r(v2 - h2));
            Alo[ks][3] = __float_as_uint(tf32r(v3 - h3));
        }
    }

    float tsA[KNN], tsB[KNN];
    int   tiA[KNN], tiB[KNN];
#pragma unroll
    for (int k = 0; k < KNN; ++k) {
        tsA[k] = BIGF; tiA[k] = 0;
        tsB[k] = BIGF; tiB[k] = 0;
    }

    // ---- stream slabs ----
    const int sg0 = sp * (NSLAB / 2) + ph * NS;        // first slab
    const float4* bp = g_Bf + (size_t)sg0 * 128;
    const float*  hp = g_hs + sg0 * 8 + 2 * tig;

    // prefetch slab 0
    float4 nb0 = bp[lane],      nb1 = bp[32 + lane];
    float4 nb2 = bp[64 + lane], nb3 = bp[96 + lane];
    float2 nhs = *(const float2*)hp;

    for (int t = 0; t < NS; ++t) {
        float4 b0 = nb0, b1 = nb1, b2 = nb2, b3 = nb3;
        float2 hsv = nhs;
        if (t + 1 < NS) {
            bp += 128; hp += 8;
            nb0 = bp[lane];      nb1 = bp[32 + lane];
            nb2 = bp[64 + lane]; nb3 = bp[96 + lane];
            nhs = *(const float2*)hp;
        }

        float c[4] = {0.f, 0.f, 0.f, 0.f};
        // hi*hi
        mma8(c, Ahi[0], __float_as_uint(b0.x), __float_as_uint(b0.y));
        mma8(c, Ahi[1], __float_as_uint(b0.z), __float_as_uint(b0.w));
        mma8(c, Ahi[2], __float_as_uint(b1.x), __float_as_uint(b1.y));
        mma8(c, Ahi[3], __float_as_uint(b1.z), __float_as_uint(b1.w));
        // hi*lo
        mma8(c, Ahi[0], __float_as_uint(b2.x), __float_as_uint(b2.y));
        mma8(c, Ahi[1], __float_as_uint(b2.z), __float_as_uint(b2.w));
        mma8(c, Ahi[2], __float_as_uint(b3.x), __float_as_uint(b3.y));
        mma8(c, Ahi[3], __float_as_uint(b3.z), __float_as_uint(b3.w));
        // lo*hi
        mma8(c, Alo[0], __float_as_uint(b0.x), __float_as_uint(b0.y));
        mma8(c, Alo[1], __float_as_uint(b0.z), __float_as_uint(b0.w));
        mma8(c, Alo[2], __float_as_uint(b1.x), __float_as_uint(b1.y));
        mma8(c, Alo[3], __float_as_uint(b1.z), __float_as_uint(b1.w));

        // scores: row r0 -> c0,c1 ; row r1 -> c2,c3 ; cols p0+2tig, +1
        const int p0 = (sg0 + t) * 8 + 2 * tig;
        topk_ins(tsA, tiA, hsv.x - c[0], p0);
        topk_ins(tsA, tiA, hsv.y - c[1], p0 + 1);
        topk_ins(tsB, tiB, hsv.x - c[2], p0);
        topk_ins(tsB, tiB, hsv.y - c[3], p0 + 1);

        if ((t & 31) == 31) __syncthreads();    // keep p-half warps in L1 window
    }

    // ---- quad-merge (4 lanes share each query) and write 5 candidates ----
#pragma unroll
    for (int l = 0; l < 2; ++l) {
        float c0 = l ? tsB[0] : tsA[0], c1 = l ? tsB[1] : tsA[1],
              c2 = l ? tsB[2] : tsA[2], c3 = l ? tsB[3] : tsA[3],
              c4 = l ? tsB[4] : tsA[4];
        int   j0 = l ? tiB[0] : tiA[0], j1 = l ? tiB[1] : tiA[1],
              j2 = l ? tiB[2] : tiA[2], j3 = l ? tiB[3] : tiA[3],
              j4 = l ? tiB[4] : tiA[4];
        const int qi = l ? r1 : r0;

#pragma unroll
        for (int k = 0; k < KNN; ++k) {
            float m  = c0;
            int   ml = lane;
            float om = __shfl_xor_sync(FULL, m, 1, 4);
            int   ol = __shfl_xor_sync(FULL, ml, 1, 4);
            if (om < m || (om == m && ol < ml)) { m = om; ml = ol; }
            om = __shfl_xor_sync(FULL, m, 2, 4);
            ol = __shfl_xor_sync(FULL, ml, 2, 4);
            if (om < m || (om == m && ol < ml)) { m = om; ml = ol; }
            int wi = __shfl_sync(FULL, j0, ml & 3, 4);
            if (lane == ml) {
                c0 = c1; c1 = c2; c2 = c3; c3 = c4; c4 = BIGF;
                j0 = j1; j1 = j2; j2 = j3; j3 = j4;
            }
            if (tig == 0) {
                g_cs[(qi * 4 + w4) * KNN + k] = m;
                g_ci[(qi * 4 + w4) * KNN + k] = wi;
            }
        }
    }
}

// ---------------------------------------------------------------------------
// merge: one warp per query; 20 candidates -> top-5 -> weighted aux gather
// ---------------------------------------------------------------------------
__global__ void merge_kernel(const float* __restrict__ q,
                             const float* __restrict__ aux,
                             float* __restrict__ out) {
    const unsigned FULL = 0xffffffffu;
    const int gw   = (blockIdx.x * blockDim.x + threadIdx.x) >> 5;
    const int lane = threadIdx.x & 31;
    if (gw >= NQ) return;

    float sc = (lane < 4 * KNN) ? g_cs[gw * 4 * KNN + lane] : BIGF;
    int   id = (lane < 4 * KNN) ? g_ci[gw * 4 * KNN + lane] : 0;

    float qv  = q[gw * DIM + lane];
    float qsq = qv * qv;
#pragma unroll
    for (int off = 16; off; off >>= 1)
        qsq += __shfl_xor_sync(FULL, qsq, off);

    float wk[KNN]; int bk[KNN];
    float wsum = 0.f;
#pragma unroll
    for (int k = 0; k < KNN; ++k) {
        float m  = sc;
        int   ml = lane;
#pragma unroll
        for (int off = 16; off; off >>= 1) {
            float om = __shfl_xor_sync(FULL, m, off);
            int   ol = __shfl_xor_sync(FULL, ml, off);
            if (om < m || (om == m && ol < ml)) { m = om; ml = ol; }
        }
        int wi = __shfl_sync(FULL, id, ml);
        float dist = sqrtf(fmaxf(qsq + 2.0f * m, 0.0f));
        float wgt  = 1.0f / (dist + 1e-6f);
        wk[k] = wgt; bk[k] = wi; wsum += wgt;
        if (lane == ml) sc = BIGF;
    }

    float acc = 0.f;
#pragma unroll
    for (int k = 0; k < KNN; ++k)
        acc += wk[k] * aux[bk[k] * DAUX + lane];
    out[gw * DAUX + lane] = acc / wsum;
}

// ---------------------------------------------------------------------------
extern "C" void kernel_launch(void* const* d_in, const int* in_sizes, int n_in,
                              void* d_out, int out_size) {
    const float* q   = (const float*)d_in[0];   // embedding_features [4096,32]
    const float* db  = (const float*)d_in[1];   // db_embedding      [65536,32]
    const float* aux = (const float*)d_in[2];   // auxiliary_features[65536,32]
    float* out = (float*)d_out;                 // [4096,32]

    prep_hs<<<NDB / 32, 256>>>(db);
    prep_bf<<<NSLAB * 64 / 256, 256>>>(db);
    knn_mma<<<(NQ / QPC) * NSPLIT, 256>>>(q);
    merge_kernel<<<NQ / 8, 256>>>(q, aux, out);
}

// round 13
// speedup vs baseline: 1.4036x; 1.4036x over previous
#include <cuda_runtime.h>
#include <cstdint>

#define NQ      4096
#define NDB     65536
#define DIM     32
#define DAUX    32
#define KNN     5
#define NSLAB   (NDB / 8)          // 8192 8-point slabs
#define NSPLIT  4                  // db quarters per query tile
#define QPC     64                 // queries per CTA (4 m-tiles)
#define NS      (NSLAB / NSPLIT / 2)  // 1024 slabs per warp (eighth of db)
#define NLIST   (NSPLIT * 2)       // 8 candidate lists per query
#define BIGF    3.0e38f

// ---------------- global scratch ----------------
// g_Bf: frag-packed db tiles. Per slab s (8 points): 128 float4 =
//   [term hi|lo][i2 0|1][lane 0..31] ; lane's float4 = B[k=tig+4*(4*i2+c)][p=s*8+lane>>2]
__device__ float4 g_Bf[NSLAB * 128];          // 16 MB
__device__ float  g_hs[NDB];                  // 0.5*||db||^2
__device__ float  g_cs[NQ * NLIST * KNN];     // 8 candidate lists of 5 per query
__device__ int    g_ci[NQ * NLIST * KNN];

// ---------------- helpers ----------------
__device__ __forceinline__ float tf32r(float x) {
    uint32_t r;
    asm("cvt.rna.tf32.f32 %0, %1;" : "=r"(r) : "f"(x));
    return __uint_as_float(r);
}
__device__ __forceinline__ void mma8(float* c, const uint32_t* a,
                                     uint32_t b0, uint32_t b1) {
    asm("mma.sync.aligned.m16n8k8.row.col.f32.tf32.tf32.f32 "
        "{%0,%1,%2,%3}, {%4,%5,%6,%7}, {%8,%9}, {%0,%1,%2,%3};"
        : "+f"(c[0]), "+f"(c[1]), "+f"(c[2]), "+f"(c[3])
        : "r"(a[0]), "r"(a[1]), "r"(a[2]), "r"(a[3]), "r"(b0), "r"(b1));
}
__device__ __forceinline__ void topk_ins(float* ts, int* ti, float s, int pi) {
    if (s < ts[4]) {
        ts[4] = s; ti[4] = pi;
        if (ts[4] < ts[3]) { float f = ts[3]; ts[3] = ts[4]; ts[4] = f; int i = ti[3]; ti[3] = ti[4]; ti[4] = i; }
        if (ts[3] < ts[2]) { float f = ts[2]; ts[2] = ts[3]; ts[3] = f; int i = ti[2]; ti[2] = ti[3]; ti[3] = i; }
        if (ts[2] < ts[1]) { float f = ts[1]; ts[1] = ts[2]; ts[2] = f; int i = ti[1]; ti[1] = ti[2]; ti[2] = i; }
        if (ts[1] < ts[0]) { float f = ts[0]; ts[0] = ts[1]; ts[1] = f; int i = ti[0]; ti[0] = ti[1]; ti[1] = i; }
    }
}

// ---------------------------------------------------------------------------
// prep_hs: 0.5*||db||^2 per point. 8 lanes per point, coalesced float4 reads.
// ---------------------------------------------------------------------------
__global__ void prep_hs(const float* __restrict__ db) {
    const unsigned FULL = 0xffffffffu;
    const int p = blockIdx.x * 32 + (threadIdx.x >> 3);
    const int j = threadIdx.x & 7;
    float4 v = *(const float4*)(db + p * DIM + j * 4);
    float s = v.x * v.x + v.y * v.y + v.z * v.z + v.w * v.w;
    s += __shfl_xor_sync(FULL, s, 4, 8);
    s += __shfl_xor_sync(FULL, s, 2, 8);
    s += __shfl_xor_sync(FULL, s, 1, 8);
    if (j == 0) g_hs[p] = 0.5f * s;
}

// ---------------------------------------------------------------------------
// prep_bf: build frag-packed hi/lo db images.
// ---------------------------------------------------------------------------
__global__ void prep_bf(const float* __restrict__ db) {
    const int gid  = blockIdx.x * 256 + threadIdx.x;   // 0 .. 8192*64-1
    const int s    = gid >> 6;
    const int r    = gid & 63;
    const int i2   = r >> 5;
    const int lane = r & 31;
    const int tig  = lane & 3;
    const int p    = s * 8 + (lane >> 2);

    float hv[4], lv[4];
#pragma unroll
    for (int c = 0; c < 4; ++c) {
        int k = tig + 4 * (i2 * 4 + c);
        float v = db[p * DIM + k];
        float h = tf32r(v);
        hv[c] = h;
        lv[c] = tf32r(v - h);
    }
    g_Bf[s * 128 +      i2 * 32 + lane] = make_float4(hv[0], hv[1], hv[2], hv[3]);
    g_Bf[s * 128 + 64 + i2 * 32 + lane] = make_float4(lv[0], lv[1], lv[2], lv[3]);
}

// ---------------------------------------------------------------------------
// main: 256 CTAs (64 q-tiles x 4 db-splits), 256 threads, 2 CTAs/SM
// (4 warps/SMSP). A in registers; B as packed frags via coalesced LDG.128.
// 12 tf32 HMMAs/slab split into THREE independent 4-deep chains.
// ---------------------------------------------------------------------------
__global__ void __launch_bounds__(256, 2)
knn_mma(const float* __restrict__ q) {
    const unsigned FULL = 0xffffffffu;
    const int tid  = threadIdx.x;
    const int lane = tid & 31;
    const int tig  = lane & 3;
    const int wid  = tid >> 5;
    const int mi   = wid & 3;              // m-tile within CTA (16 queries)
    const int ph   = wid >> 2;             // p-half within this CTA's db split
    const int qb   = blockIdx.x >> 2;      // 0..63 query tile
    const int sp   = blockIdx.x & 3;       // db split (quarter)
    const int w8   = sp * 2 + ph;          // candidate-list slot 0..7

    const int r0 = qb * QPC + mi * 16 + (lane >> 2);  // this thread's 2 queries
    const int r1 = r0 + 8;

    // ---- load A fragments (hi/lo), resident for the whole kernel ----
    uint32_t Ahi[4][4], Alo[4][4];
    {
        const float* q0 = q + r0 * DIM;
        const float* q1 = q + r1 * DIM;
#pragma unroll
        for (int ks = 0; ks < 4; ++ks) {
            int k0 = 8 * ks + tig;
            float v0 = q0[k0], v1 = q1[k0], v2 = q0[k0 + 4], v3 = q1[k0 + 4];
            float h0 = tf32r(v0), h1 = tf32r(v1), h2 = tf32r(v2), h3 = tf32r(v3);
            Ahi[ks][0] = __float_as_uint(h0);
            Ahi[ks][1] = __float_as_uint(h1);
            Ahi[ks][2] = __float_as_uint(h2);
            Ahi[ks][3] = __float_as_uint(h3);
            Alo[ks][0] = __float_as_uint(tf32r(v0 - h0));
            Alo[ks][1] = __float_as_uint(tf32r(v1 - h1));
            Alo[ks][2] = __float_as_uint(tf32r(v2 - h2));
            Alo[ks][3] = __float_as_uint(tf32r(v3 - h3));
        }
    }

    float tsA[KNN], tsB[KNN];
    int   tiA[KNN], tiB[KNN];
#pragma unroll
    for (int k = 0; k < KNN; ++k) {
        tsA[k] = BIGF; tiA[k] = 0;
        tsB[k] = BIGF; tiB[k] = 0;
    }

    // ---- stream slabs ----
    const int sg0 = sp * (NSLAB / NSPLIT) + ph * NS;   // first slab
    const float4* bp = g_Bf + (size_t)sg0 * 128;
    const float*  hp = g_hs + sg0 * 8 + 2 * tig;

    // prefetch slab 0
    float4 nb0 = bp[lane],      nb1 = bp[32 + lane];
    float4 nb2 = bp[64 + lane], nb3 = bp[96 + lane];
    float2 nhs = *(const float2*)hp;

    for (int t = 0; t < NS; ++t) {
        float4 b0 = nb0, b1 = nb1, b2 = nb2, b3 = nb3;
        float2 hsv = nhs;
        if (t + 1 < NS) {
            bp += 128; hp += 8;
            nb0 = bp[lane];      nb1 = bp[32 + lane];
            nb2 = bp[64 + lane]; nb3 = bp[96 + lane];
            nhs = *(const float2*)hp;
        }

        // THREE independent accumulator chains (depth 4 each)
        float chh[4] = {0.f, 0.f, 0.f, 0.f};
        float chl[4] = {0.f, 0.f, 0.f, 0.f};
        float clh[4] = {0.f, 0.f, 0.f, 0.f};
        // hi*hi
        mma8(chh, Ahi[0], __float_as_uint(b0.x), __float_as_uint(b0.y));
        mma8(chl, Ahi[0], __float_as_uint(b2.x), __float_as_uint(b2.y));
        mma8(clh, Alo[0], __float_as_uint(b0.x), __float_as_uint(b0.y));
        mma8(chh, Ahi[1], __float_as_uint(b0.z), __float_as_uint(b0.w));
        mma8(chl, Ahi[1], __float_as_uint(b2.z), __float_as_uint(b2.w));
        mma8(clh, Alo[1], __float_as_uint(b0.z), __float_as_uint(b0.w));
        mma8(chh, Ahi[2], __float_as_uint(b1.x), __float_as_uint(b1.y));
        mma8(chl, Ahi[2], __float_as_uint(b3.x), __float_as_uint(b3.y));
        mma8(clh, Alo[2], __float_as_uint(b1.x), __float_as_uint(b1.y));
        mma8(chh, Ahi[3], __float_as_uint(b1.z), __float_as_uint(b1.w));
        mma8(chl, Ahi[3], __float_as_uint(b3.z), __float_as_uint(b3.w));
        mma8(clh, Alo[3], __float_as_uint(b1.z), __float_as_uint(b1.w));

        float c0 = chh[0] + chl[0] + clh[0];
        float c1 = chh[1] + chl[1] + clh[1];
        float c2 = chh[2] + chl[2] + clh[2];
        float c3 = chh[3] + chl[3] + clh[3];

        // scores: row r0 -> c0,c1 ; row r1 -> c2,c3 ; cols p0+2tig, +1
        const int p0 = (sg0 + t) * 8 + 2 * tig;
        topk_ins(tsA, tiA, hsv.x - c0, p0);
        topk_ins(tsA, tiA, hsv.y - c1, p0 + 1);
        topk_ins(tsB, tiB, hsv.x - c2, p0);
        topk_ins(tsB, tiB, hsv.y - c3, p0 + 1);

        if ((t & 31) == 31) __syncthreads();    // keep warps in L1 window
    }

    // ---- quad-merge (4 lanes share each query) and write 5 candidates ----
#pragma unroll
    for (int l = 0; l < 2; ++l) {
        float c0 = l ? tsB[0] : tsA[0], c1 = l ? tsB[1] : tsA[1],
              c2 = l ? tsB[2] : tsA[2], c3 = l ? tsB[3] : tsA[3],
              c4 = l ? tsB[4] : tsA[4];
        int   j0 = l ? tiB[0] : tiA[0], j1 = l ? tiB[1] : tiA[1],
              j2 = l ? tiB[2] : tiA[2], j3 = l ? tiB[3] : tiA[3],
              j4 = l ? tiB[4] : tiA[4];
        const int qi = l ? r1 : r0;

#pragma unroll
        for (int k = 0; k < KNN; ++k) {
            float m  = c0;
            int   ml = lane;
            float om = __shfl_xor_sync(FULL, m, 1, 4);
            int   ol = __shfl_xor_sync(FULL, ml, 1, 4);
            if (om < m || (om == m && ol < ml)) { m = om; ml = ol; }
            om = __shfl_xor_sync(FULL, m, 2, 4);
            ol = __shfl_xor_sync(FULL, ml, 2, 4);
            if (om < m || (om == m && ol < ml)) { m = om; ml = ol; }
            int wi = __shfl_sync(FULL, j0, ml & 3, 4);
            if (lane == ml) {
                c0 = c1; c1 = c2; c2 = c3; c3 = c4; c4 = BIGF;
                j0 = j1; j1 = j2; j2 = j3; j3 = j4;
            }
            if (tig == 0) {
                g_cs[(qi * NLIST + w8) * KNN + k] = m;
                g_ci[(qi * NLIST + w8) * KNN + k] = wi;
            }
        }
    }
}

// ---------------------------------------------------------------------------
// merge: one warp per query; 40 candidates (2 per lane, sorted) -> top-5
// -> weighted aux gather
// ---------------------------------------------------------------------------
__global__ void merge_kernel(const float* __restrict__ q,
                             const float* __restrict__ aux,
                             float* __restrict__ out) {
    const unsigned FULL = 0xffffffffu;
    const int gw   = (blockIdx.x * blockDim.x + threadIdx.x) >> 5;
    const int lane = threadIdx.x & 31;
    if (gw >= NQ) return;

    const int NC = NLIST * KNN;                 // 40
    float clo = g_cs[gw * NC + lane];
    int   ilo = g_ci[gw * NC + lane];
    float chi = (lane < NC - 32) ? g_cs[gw * NC + 32 + lane] : BIGF;
    int   ihi = (lane < NC - 32) ? g_ci[gw * NC + 32 + lane] : 0;
    if (chi < clo) { float f = clo; clo = chi; chi = f; int i = ilo; ilo = ihi; ihi = i; }

    float qv  = q[gw * DIM + lane];
    float qsq = qv * qv;
#pragma unroll
    for (int off = 16; off; off >>= 1)
        qsq += __shfl_xor_sync(FULL, qsq, off);

    float wk[KNN]; int bk[KNN];
    float wsum = 0.f;
#pragma unroll
    for (int k = 0; k < KNN; ++k) {
        float m  = clo;
        int   ml = lane;
#pragma unroll
        for (int off = 16; off; off >>= 1) {
            float om = __shfl_xor_sync(FULL, m, off);
            int   ol = __shfl_xor_sync(FULL, ml, off);
            if (om < m || (om == m && ol < ml)) { m = om; ml = ol; }
        }
        int wi = __shfl_sync(FULL, ilo, ml);
        float dist = sqrtf(fmaxf(qsq + 2.0f * m, 0.0f));
        float wgt  = 1.0f / (dist + 1e-6f);
        wk[k] = wgt; bk[k] = wi; wsum += wgt;
        if (lane == ml) { clo = chi; ilo = ihi; chi = BIGF; }
    }

    float acc = 0.f;
#pragma unroll
    for (int k = 0; k < KNN; ++k)
        acc += wk[k] * aux[bk[k] * DAUX + lane];
    out[gw * DAUX + lane] = acc / wsum;
}

// ---------------------------------------------------------------------------
extern "C" void kernel_launch(void* const* d_in, const int* in_sizes, int n_in,
                              void* d_out, int out_size) {
    const float* q   = (const float*)d_in[0];   // embedding_features [4096,32]
    const float* db  = (const float*)d_in[1];   // db_embedding      [65536,32]
    const float* aux = (const float*)d_in[2];   // auxiliary_features[65536,32]
    float* out = (float*)d_out;                 // [4096,32]

    prep_hs<<<NDB / 32, 256>>>(db);
    prep_bf<<<NSLAB * 64 / 256, 256>>>(db);
    knn_mma<<<(NQ / QPC) * NSPLIT, 256>>>(q);
    merge_kernel<<<NQ / 8, 256>>>(q, aux, out);
}

// round 14
// speedup vs baseline: 1.8541x; 1.3210x over previous
#include <cuda_runtime.h>
#include <cuda_fp16.h>
#include <cstdint>

#define NQ      4096
#define NDB     65536
#define DIM     32
#define DAUX    32
#define KNN     5
#define NSLAB   (NDB / 8)          // 8192 8-point slabs
#define NSPLIT  4                  // db quarters per query tile
#define QPC     64                 // queries per CTA (4 m-tiles)
#define NS      (NSLAB / NSPLIT / 2)  // 1024 slabs per warp (eighth of db)
#define NLIST   (NSPLIT * 2)       // 8 candidate lists per query
#define BIGF    3.0e38f

// ---------------- global scratch ----------------
// g_Bf: fp16 frag-packed db. Per slab s (8 points): 64 uint4 =
//   [hi lane0..31][lo lane0..31]; lane uint4 = {ks0.b0, ks0.b1, ks1.b0, ks1.b1}
//   where b-halves are db[k][p], p = s*8 + lane>>2, k per m16n8k16 B layout.
__device__ uint4 g_Bf[NSLAB * 64];            // 8 MB
__device__ float g_hs[NDB];                   // 0.5*||db||^2
__device__ float g_cs[NQ * NLIST * KNN];
__device__ int   g_ci[NQ * NLIST * KNN];

// ---------------- helpers ----------------
__device__ __forceinline__ uint32_t h2u(__half a, __half b) {
    __half2 h = __halves2half2(a, b);
    return *(uint32_t*)&h;
}
__device__ __forceinline__ void mma16(float* c, const uint32_t* a,
                                      uint32_t b0, uint32_t b1) {
    asm("mma.sync.aligned.m16n8k16.row.col.f32.f16.f16.f32 "
        "{%0,%1,%2,%3}, {%4,%5,%6,%7}, {%8,%9}, {%0,%1,%2,%3};"
        : "+f"(c[0]), "+f"(c[1]), "+f"(c[2]), "+f"(c[3])
        : "r"(a[0]), "r"(a[1]), "r"(a[2]), "r"(a[3]), "r"(b0), "r"(b1));
}
__device__ __forceinline__ void topk_ins(float* ts, int* ti, float s, int pi) {
    if (s < ts[4]) {
        ts[4] = s; ti[4] = pi;
        if (ts[4] < ts[3]) { float f = ts[3]; ts[3] = ts[4]; ts[4] = f; int i = ti[3]; ti[3] = ti[4]; ti[4] = i; }
        if (ts[3] < ts[2]) { float f = ts[2]; ts[2] = ts[3]; ts[3] = f; int i = ti[2]; ti[2] = ti[3]; ti[3] = i; }
        if (ts[2] < ts[1]) { float f = ts[1]; ts[1] = ts[2]; ts[2] = f; int i = ti[1]; ti[1] = ti[2]; ti[2] = i; }
        if (ts[1] < ts[0]) { float f = ts[0]; ts[0] = ts[1]; ts[1] = f; int i = ti[0]; ti[0] = ti[1]; ti[1] = i; }
    }
}

// ---------------------------------------------------------------------------
// prep_hs: 0.5*||db||^2 per point. 8 lanes per point, coalesced float4 reads.
// ---------------------------------------------------------------------------
__global__ void prep_hs(const float* __restrict__ db) {
    const unsigned FULL = 0xffffffffu;
    const int p = blockIdx.x * 32 + (threadIdx.x >> 3);
    const int j = threadIdx.x & 7;
    float4 v = *(const float4*)(db + p * DIM + j * 4);
    float s = v.x * v.x + v.y * v.y + v.z * v.z + v.w * v.w;
    s += __shfl_xor_sync(FULL, s, 4, 8);
    s += __shfl_xor_sync(FULL, s, 2, 8);
    s += __shfl_xor_sync(FULL, s, 1, 8);
    if (j == 0) g_hs[p] = 0.5f * s;
}

// ---------------------------------------------------------------------------
// prep_bf: build fp16 hi/lo frag-packed db images. One thread per (slab, lane).
// ---------------------------------------------------------------------------
__global__ void prep_bf(const float* __restrict__ db) {
    const int gid  = blockIdx.x * 256 + threadIdx.x;   // 0 .. NSLAB*32-1
    const int s    = gid >> 5;
    const int lane = gid & 31;
    const int tig  = lane & 3;
    const int p    = s * 8 + (lane >> 2);

    const float* src = db + p * DIM;
    __half hi[8], lo[8];
#pragma unroll
    for (int e = 0; e < 8; ++e) {
        // k-order: {2t,2t+1, 2t+8,2t+9, 2t+16,2t+17, 2t+24,2t+25}
        int k = 2 * tig + (e & 1) + 8 * (e >> 1);
        float v = src[k];
        __half h = __float2half_rn(v);
        hi[e] = h;
        lo[e] = __float2half_rn(v - __half2float(h));
    }
    uint4 uh, ul;
    uh.x = h2u(hi[0], hi[1]); uh.y = h2u(hi[2], hi[3]);
    uh.z = h2u(hi[4], hi[5]); uh.w = h2u(hi[6], hi[7]);
    ul.x = h2u(lo[0], lo[1]); ul.y = h2u(lo[2], lo[3]);
    ul.z = h2u(lo[4], lo[5]); ul.w = h2u(lo[6], lo[7]);
    g_Bf[s * 64 + lane]      = uh;
    g_Bf[s * 64 + 32 + lane] = ul;
}

// ---------------------------------------------------------------------------
// main: 256 CTAs (64 q-tiles x 4 db-splits), 256 threads, 2 CTAs/SM.
// A (queries, fp16 hi/lo) in registers; B packed frags via 2 coalesced
// LDG.128/slab; 6 fp16 m16n8k16 MMAs/slab in 3 independent depth-2 chains.
// ---------------------------------------------------------------------------
__global__ void __launch_bounds__(256, 2)
knn_mma(const float* __restrict__ q) {
    const unsigned FULL = 0xffffffffu;
    const int tid  = threadIdx.x;
    const int lane = tid & 31;
    const int tig  = lane & 3;
    const int wid  = tid >> 5;
    const int mi   = wid & 3;              // m-tile within CTA (16 queries)
    const int ph   = wid >> 2;             // p-half within this CTA's db split
    const int qb   = blockIdx.x >> 2;      // 0..63 query tile
    const int sp   = blockIdx.x & 3;       // db split (quarter)
    const int w8   = sp * 2 + ph;          // candidate-list slot 0..7

    const int r0 = qb * QPC + mi * 16 + (lane >> 2);  // this thread's 2 queries
    const int r1 = r0 + 8;

    // ---- A fragments (hi/lo), resident: Axx[ks][a0..a3] ----
    uint32_t Ahi[2][4], Alo[2][4];
    {
        const float* q0 = q + r0 * DIM;
        const float* q1 = q + r1 * DIM;
#pragma unroll
        for (int ks = 0; ks < 2; ++ks) {
            int kb = 16 * ks + 2 * tig;
            float v00 = q0[kb],     v01 = q0[kb + 1];
            float v10 = q1[kb],     v11 = q1[kb + 1];
            float v02 = q0[kb + 8], v03 = q0[kb + 9];
            float v12 = q1[kb + 8], v13 = q1[kb + 9];
            __half h00 = __float2half_rn(v00), h01 = __float2half_rn(v01);
            __half h10 = __float2half_rn(v10), h11 = __float2half_rn(v11);
            __half h02 = __float2half_rn(v02), h03 = __float2half_rn(v03);
            __half h12 = __float2half_rn(v12), h13 = __float2half_rn(v13);
            Ahi[ks][0] = h2u(h00, h01);
            Ahi[ks][1] = h2u(h10, h11);
            Ahi[ks][2] = h2u(h02, h03);
            Ahi[ks][3] = h2u(h12, h13);
            Alo[ks][0] = h2u(__float2half_rn(v00 - __half2float(h00)),
                             __float2half_rn(v01 - __half2float(h01)));
            Alo[ks][1] = h2u(__float2half_rn(v10 - __half2float(h10)),
                             __float2half_rn(v11 - __half2float(h11)));
            Alo[ks][2] = h2u(__float2half_rn(v02 - __half2float(h02)),
                             __float2half_rn(v03 - __half2float(h03)));
            Alo[ks][3] = h2u(__float2half_rn(v12 - __half2float(h12)),
                             __float2half_rn(v13 - __half2float(h13)));
        }
    }

    float tsA[KNN], tsB[KNN];
    int   tiA[KNN], tiB[KNN];
#pragma unroll
    for (int k = 0; k < KNN; ++k) {
        tsA[k] = BIGF; tiA[k] = 0;
        tsB[k] = BIGF; tiB[k] = 0;
    }

    // ---- stream slabs ----
    const int sg0 = sp * (NSLAB / NSPLIT) + ph * NS;   // first slab
    const uint4* bp = g_Bf + (size_t)sg0 * 64;
    const float* hp = g_hs + sg0 * 8 + 2 * tig;

    // prefetch slab 0
    uint4 nbh = bp[lane], nbl = bp[32 + lane];
    float2 nhs = *(const float2*)hp;

    for (int t = 0; t < NS; ++t) {
        uint4 bh = nbh, bl = nbl;
        float2 hsv = nhs;
        if (t + 1 < NS) {
            bp += 64; hp += 8;
            nbh = bp[lane];
            nbl = bp[32 + lane];
            nhs = *(const float2*)hp;
        }

        // three independent chains, depth 2
        float chh[4] = {0.f, 0.f, 0.f, 0.f};
        float chl[4] = {0.f, 0.f, 0.f, 0.f};
        float clh[4] = {0.f, 0.f, 0.f, 0.f};
        mma16(chh, Ahi[0], bh.x, bh.y);
        mma16(chl, Ahi[0], bl.x, bl.y);
        mma16(clh, Alo[0], bh.x, bh.y);
        mma16(chh, Ahi[1], bh.z, bh.w);
        mma16(chl, Ahi[1], bl.z, bl.w);
        mma16(clh, Alo[1], bh.z, bh.w);

        float c0 = chh[0] + chl[0] + clh[0];
        float c1 = chh[1] + chl[1] + clh[1];
        float c2 = chh[2] + chl[2] + clh[2];
        float c3 = chh[3] + chl[3] + clh[3];

        // scores: row r0 -> c0,c1 ; row r1 -> c2,c3 ; cols p0+2tig, +1
        const int p0 = (sg0 + t) * 8 + 2 * tig;
        topk_ins(tsA, tiA, hsv.x - c0, p0);
        topk_ins(tsA, tiA, hsv.y - c1, p0 + 1);
        topk_ins(tsB, tiB, hsv.x - c2, p0);
        topk_ins(tsB, tiB, hsv.y - c3, p0 + 1);

        if ((t & 31) == 31) __syncthreads();    // keep warps in L1 window
    }

    // ---- quad-merge (4 lanes share each query) and write 5 candidates ----
#pragma unroll
    for (int l = 0; l < 2; ++l) {
        float c0 = l ? tsB[0] : tsA[0], c1 = l ? tsB[1] : tsA[1],
              c2 = l ? tsB[2] : tsA[2], c3 = l ? tsB[3] : tsA[3],
              c4 = l ? tsB[4] : tsA[4];
        int   j0 = l ? tiB[0] : tiA[0], j1 = l ? tiB[1] : tiA[1],
              j2 = l ? tiB[2] : tiA[2], j3 = l ? tiB[3] : tiA[3],
              j4 = l ? tiB[4] : tiA[4];
        const int qi = l ? r1 : r0;

#pragma unroll
        for (int k = 0; k < KNN; ++k) {
            float m  = c0;
            int   ml = lane;
            float om = __shfl_xor_sync(FULL, m, 1, 4);
            int   ol = __shfl_xor_sync(FULL, ml, 1, 4);
            if (om < m || (om == m && ol < ml)) { m = om; ml = ol; }
            om = __shfl_xor_sync(FULL, m, 2, 4);
            ol = __shfl_xor_sync(FULL, ml, 2, 4);
            if (om < m || (om == m && ol < ml)) { m = om; ml = ol; }
            int wi = __shfl_sync(FULL, j0, ml & 3, 4);
            if (lane == ml) {
                c0 = c1; c1 = c2; c2 = c3; c3 = c4; c4 = BIGF;
                j0 = j1; j1 = j2; j2 = j3; j3 = j4;
            }
            if (tig == 0) {
                g_cs[(qi * NLIST + w8) * KNN + k] = m;
                g_ci[(qi * NLIST + w8) * KNN + k] = wi;
            }
        }
    }
}

// ---------------------------------------------------------------------------
// merge: one warp per query; 40 candidates (2 per lane, sorted) -> top-5
// -> weighted aux gather
// ---------------------------------------------------------------------------
__global__ void merge_kernel(const float* __restrict__ q,
                             const float* __restrict__ aux,
                             float* __restrict__ out) {
    const unsigned FULL = 0xffffffffu;
    const int gw   = (blockIdx.x * blockDim.x + threadIdx.x) >> 5;
    const int lane = threadIdx.x & 31;
    if (gw >= NQ) return;

    const int NC = NLIST * KNN;                 // 40
    float clo = g_cs[gw * NC + lane];
    int   ilo = g_ci[gw * NC + lane];
    float chi = (lane < NC - 32) ? g_cs[gw * NC + 32 + lane] : BIGF;
    int   ihi = (lane < NC - 32) ? g_ci[gw * NC + 32 + lane] : 0;
    if (chi < clo) { float f = clo; clo = chi; chi = f; int i = ilo; ilo = ihi; ihi = i; }

    float qv  = q[gw * DIM + lane];
    float qsq = qv * qv;
#pragma unroll
    for (int off = 16; off; off >>= 1)
        qsq += __shfl_xor_sync(FULL, qsq, off);

    float wk[KNN]; int bk[KNN];
    float wsum = 0.f;
#pragma unroll
    for (int k = 0; k < KNN; ++k) {
        float m  = clo;
        int   ml = lane;
#pragma unroll
        for (int off = 16; off; off >>= 1) {
            float om = __shfl_xor_sync(FULL, m, off);
            int   ol = __shfl_xor_sync(FULL, ml, off);
            if (om < m || (om == m && ol < ml)) { m = om; ml = ol; }
        }
        int wi = __shfl_sync(FULL, ilo, ml);
        float dist = sqrtf(fmaxf(qsq + 2.0f * m, 0.0f));
        float wgt  = 1.0f / (dist + 1e-6f);
        wk[k] = wgt; bk[k] = wi; wsum += wgt;
        if (lane == ml) { clo = chi; ilo = ihi; chi = BIGF; }
    }

    float acc = 0.f;
#pragma unroll
    for (int k = 0; k < KNN; ++k)
        acc += wk[k] * aux[bk[k] * DAUX + lane];
    out[gw * DAUX + lane] = acc / wsum;
}

// ---------------------------------------------------------------------------
extern "C" void kernel_launch(void* const* d_in, const int* in_sizes, int n_in,
                              void* d_out, int out_size) {
    const float* q   = (const float*)d_in[0];   // embedding_features [4096,32]
    const float* db  = (const float*)d_in[1];   // db_embedding      [65536,32]
    const float* aux = (const float*)d_in[2];   // auxiliary_features[65536,32]
    float* out = (float*)d_out;                 // [4096,32]

    prep_hs<<<NDB / 32, 256>>>(db);
    prep_bf<<<NSLAB * 32 / 256, 256>>>(db);
    knn_mma<<<(NQ / QPC) * NSPLIT, 256>>>(q);
    merge_kernel<<<NQ / 8, 256>>>(q, aux, out);
}

// round 15
// speedup vs baseline: 2.5997x; 1.4022x over previous
#include <cuda_runtime.h>
#include <cuda_fp16.h>
#include <cstdint>

#define NQ      4096
#define NDB     65536
#define DIM     32
#define DAUX    32
#define KNN     5
#define NSLAB   (NDB / 16)         // 4096 16-point slabs
#define NSPLIT  4                  // db quarters per query tile
#define QPC     64                 // queries per CTA (4 m-tiles)
#define NS      (NSLAB / NSPLIT / 2)  // 512 slabs per warp (eighth of db)
#define NLIST   (NSPLIT * 2)       // 8 candidate lists per query
#define BIGF    3.0e38f

// ---------------- global scratch ----------------
// g_Bf: fp16 hi frag-packed db. Per 16-pt slab s: 64 uint4 =
//   [ntile j=0|1][lane 0..31]; lane uint4 = {ks0.b0, ks0.b1, ks1.b0, ks1.b1}
//   for point p = s*16 + j*8 + (lane>>2), k per m16n8k16 B layout.
__device__ uint4 g_Bf[NSLAB * 64];            // 4 MB
__device__ float g_hs[NDB];                   // 0.5*||db||^2
__device__ int   g_ci[NQ * NLIST * KNN];      // candidate indices

// ---------------- helpers ----------------
__device__ __forceinline__ uint32_t h2u(__half a, __half b) {
    __half2 h = __halves2half2(a, b);
    return *(uint32_t*)&h;
}
__device__ __forceinline__ void mma16(float* c, const uint32_t* a,
                                      uint32_t b0, uint32_t b1) {
    asm("mma.sync.aligned.m16n8k16.row.col.f32.f16.f16.f32 "
        "{%0,%1,%2,%3}, {%4,%5,%6,%7}, {%8,%9}, {%0,%1,%2,%3};"
        : "+f"(c[0]), "+f"(c[1]), "+f"(c[2]), "+f"(c[3])
        : "r"(a[0]), "r"(a[1]), "r"(a[2]), "r"(a[3]), "r"(b0), "r"(b1));
}
__device__ __forceinline__ void topk_ins(float* ts, int* ti, float s, int pi) {
    if (s < ts[4]) {
        ts[4] = s; ti[4] = pi;
        if (ts[4] < ts[3]) { float f = ts[3]; ts[3] = ts[4]; ts[4] = f; int i = ti[3]; ti[3] = ti[4]; ti[4] = i; }
        if (ts[3] < ts[2]) { float f = ts[2]; ts[2] = ts[3]; ts[3] = f; int i = ti[2]; ti[2] = ti[3]; ti[3] = i; }
        if (ts[2] < ts[1]) { float f = ts[1]; ts[1] = ts[2]; ts[2] = f; int i = ti[1]; ti[1] = ti[2]; ti[2] = i; }
        if (ts[1] < ts[0]) { float f = ts[0]; ts[0] = ts[1]; ts[1] = f; int i = ti[0]; ti[0] = ti[1]; ti[1] = i; }
    }
}

// ---------------------------------------------------------------------------
// prep_hs: 0.5*||db||^2 per point.
// ---------------------------------------------------------------------------
__global__ void prep_hs(const float* __restrict__ db) {
    const unsigned FULL = 0xffffffffu;
    const int p = blockIdx.x * 32 + (threadIdx.x >> 3);
    const int j = threadIdx.x & 7;
    float4 v = *(const float4*)(db + p * DIM + j * 4);
    float s = v.x * v.x + v.y * v.y + v.z * v.z + v.w * v.w;
    s += __shfl_xor_sync(FULL, s, 4, 8);
    s += __shfl_xor_sync(FULL, s, 2, 8);
    s += __shfl_xor_sync(FULL, s, 1, 8);
    if (j == 0) g_hs[p] = 0.5f * s;
}

// ---------------------------------------------------------------------------
// prep_bf: fp16 hi frag-packed db. One thread per (slab, ntile, lane).
// ---------------------------------------------------------------------------
__global__ void prep_bf(const float* __restrict__ db) {
    const int gid  = blockIdx.x * 256 + threadIdx.x;   // 0 .. NSLAB*64-1
    const int s    = gid >> 6;
    const int r    = gid & 63;
    const int j    = r >> 5;
    const int lane = r & 31;
    const int tig  = lane & 3;
    const int p    = s * 16 + j * 8 + (lane >> 2);

    const float* src = db + p * DIM;
    __half hi[8];
#pragma unroll
    for (int e = 0; e < 8; ++e) {
        // k-order: {2t,2t+1, 2t+8,2t+9, 2t+16,2t+17, 2t+24,2t+25}
        int k = 2 * tig + (e & 1) + 8 * (e >> 1);
        hi[e] = __float2half_rn(src[k]);
    }
    uint4 uh;
    uh.x = h2u(hi[0], hi[1]); uh.y = h2u(hi[2], hi[3]);
    uh.z = h2u(hi[4], hi[5]); uh.w = h2u(hi[6], hi[7]);
    g_Bf[s * 64 + j * 32 + lane] = uh;
}

// ---------------------------------------------------------------------------
// main: 256 CTAs (64 q-tiles x 4 db-splits), 256 threads, 2 CTAs/SM.
// hi-only fp16 scoring: per 16-pt slab, 4 MMAs in 2 independent chains.
// Candidate sets only; exact distances recomputed in merge.
// ---------------------------------------------------------------------------
__global__ void __launch_bounds__(256, 2)
knn_mma(const float* __restrict__ q) {
    const unsigned FULL = 0xffffffffu;
    const int tid  = threadIdx.x;
    const int lane = tid & 31;
    const int tig  = lane & 3;
    const int wid  = tid >> 5;
    const int mi   = wid & 3;              // m-tile within CTA (16 queries)
    const int ph   = wid >> 2;             // p-half within this CTA's db split
    const int qb   = blockIdx.x >> 2;      // 0..63 query tile
    const int sp   = blockIdx.x & 3;       // db split (quarter)
    const int w8   = sp * 2 + ph;          // candidate-list slot 0..7

    const int r0 = qb * QPC + mi * 16 + (lane >> 2);  // this thread's 2 queries
    const int r1 = r0 + 8;

    // ---- A fragments (hi only): Ahi[ks][a0..a3] ----
    uint32_t Ahi[2][4];
    {
        const float* q0 = q + r0 * DIM;
        const float* q1 = q + r1 * DIM;
#pragma unroll
        for (int ks = 0; ks < 2; ++ks) {
            int kb = 16 * ks + 2 * tig;
            Ahi[ks][0] = h2u(__float2half_rn(q0[kb]),     __float2half_rn(q0[kb + 1]));
            Ahi[ks][1] = h2u(__float2half_rn(q1[kb]),     __float2half_rn(q1[kb + 1]));
            Ahi[ks][2] = h2u(__float2half_rn(q0[kb + 8]), __float2half_rn(q0[kb + 9]));
            Ahi[ks][3] = h2u(__float2half_rn(q1[kb + 8]), __float2half_rn(q1[kb + 9]));
        }
    }

    float tsA[KNN], tsB[KNN];
    int   tiA[KNN], tiB[KNN];
#pragma unroll
    for (int k = 0; k < KNN; ++k) {
        tsA[k] = BIGF; tiA[k] = 0;
        tsB[k] = BIGF; tiB[k] = 0;
    }

    // ---- stream 16-point slabs ----
    const int sg0 = sp * (NSLAB / NSPLIT) + ph * NS;   // first slab
    const uint4* bp = g_Bf + (size_t)sg0 * 64;
    const float* hp = g_hs + sg0 * 16 + 2 * tig;

    // prefetch slab 0
    uint4  nb0 = bp[lane], nb1 = bp[32 + lane];
    float2 nh0 = *(const float2*)hp;
    float2 nh1 = *(const float2*)(hp + 8);

    for (int t = 0; t < NS; ++t) {
        uint4  b0 = nb0, b1 = nb1;
        float2 h0 = nh0, h1 = nh1;
        if (t + 1 < NS) {
            bp += 64; hp += 16;
            nb0 = bp[lane];
            nb1 = bp[32 + lane];
            nh0 = *(const float2*)hp;
            nh1 = *(const float2*)(hp + 8);
        }

        // two independent chains (one per n-tile), depth 2
        float cA[4] = {0.f, 0.f, 0.f, 0.f};
        float cB[4] = {0.f, 0.f, 0.f, 0.f};
        mma16(cA, Ahi[0], b0.x, b0.y);
        mma16(cB, Ahi[0], b1.x, b1.y);
        mma16(cA, Ahi[1], b0.z, b0.w);
        mma16(cB, Ahi[1], b1.z, b1.w);

        // approx score = 0.5||db||^2 - q.db (selection only)
        const int p0 = (sg0 + t) * 16 + 2 * tig;
        topk_ins(tsA, tiA, h0.x - cA[0], p0);
        topk_ins(tsA, tiA, h0.y - cA[1], p0 + 1);
        topk_ins(tsB, tiB, h0.x - cA[2], p0);
        topk_ins(tsB, tiB, h0.y - cA[3], p0 + 1);
        topk_ins(tsA, tiA, h1.x - cB[0], p0 + 8);
        topk_ins(tsA, tiA, h1.y - cB[1], p0 + 9);
        topk_ins(tsB, tiB, h1.x - cB[2], p0 + 8);
        topk_ins(tsB, tiB, h1.y - cB[3], p0 + 9);

        if ((t & 31) == 31) __syncthreads();    // keep warps in L1 window
    }

    // ---- quad-merge (4 lanes share each query); write 5 indices per list ----
#pragma unroll
    for (int l = 0; l < 2; ++l) {
        float c0 = l ? tsB[0] : tsA[0], c1 = l ? tsB[1] : tsA[1],
              c2 = l ? tsB[2] : tsA[2], c3 = l ? tsB[3] : tsA[3],
              c4 = l ? tsB[4] : tsA[4];
        int   j0 = l ? tiB[0] : tiA[0], j1 = l ? tiB[1] : tiA[1],
              j2 = l ? tiB[2] : tiA[2], j3 = l ? tiB[3] : tiA[3],
              j4 = l ? tiB[4] : tiA[4];
        const int qi = l ? r1 : r0;

#pragma unroll
        for (int k = 0; k < KNN; ++k) {
            float m  = c0;
            int   ml = lane;
            float om = __shfl_xor_sync(FULL, m, 1, 4);
            int   ol = __shfl_xor_sync(FULL, ml, 1, 4);
            if (om < m || (om == m && ol < ml)) { m = om; ml = ol; }
            om = __shfl_xor_sync(FULL, m, 2, 4);
            ol = __shfl_xor_sync(FULL, ml, 2, 4);
            if (om < m || (om == m && ol < ml)) { m = om; ml = ol; }
            int wi = __shfl_sync(FULL, j0, ml & 3, 4);
            if (lane == ml) {
                c0 = c1; c1 = c2; c2 = c3; c3 = c4; c4 = BIGF;
                j0 = j1; j1 = j2; j2 = j3; j3 = j4;
            }
            if (tig == 0)
                g_ci[(qi * NLIST + w8) * KNN + k] = wi;
        }
    }
}

// ---------------------------------------------------------------------------
// merge: one warp per query; 40 candidate indices -> EXACT fp32 distances
// -> top-5 -> weighted aux gather
// ---------------------------------------------------------------------------
__device__ __forceinline__ float dist2(const float* __restrict__ q,
                                       const float* __restrict__ db,
                                       int gw, int pi) {
    float s = 0.f;
#pragma unroll
    for (int d = 0; d < 8; ++d) {
        float4 a = *(const float4*)(q + gw * DIM + d * 4);
        float4 b = *(const float4*)(db + pi * DIM + d * 4);
        float dx = a.x - b.x, dy = a.y - b.y, dz = a.z - b.z, dw = a.w - b.w;
        s += dx * dx + dy * dy + dz * dz + dw * dw;
    }
    return s;
}

__global__ void merge_kernel(const float* __restrict__ q,
                             const float* __restrict__ db,
                             const float* __restrict__ aux,
                             float* __restrict__ out) {
    const unsigned FULL = 0xffffffffu;
    const int gw   = (blockIdx.x * blockDim.x + threadIdx.x) >> 5;
    const int lane = threadIdx.x & 31;
    if (gw >= NQ) return;

    const int NC = NLIST * KNN;                 // 40
    int   ilo = g_ci[gw * NC + lane];
    int   ihi = (lane < NC - 32) ? g_ci[gw * NC + 32 + lane] : 0;

    // exact squared distances (disjoint db ranges -> no duplicate indices)
    float clo = dist2(q, db, gw, ilo);
    float chi = (lane < NC - 32) ? dist2(q, db, gw, ihi) : BIGF;
    if (chi < clo) { float f = clo; clo = chi; chi = f; int i = ilo; ilo = ihi; ihi = i; }

    float wk[KNN]; int bk[KNN];
    float wsum = 0.f;
#pragma unroll
    for (int k = 0; k < KNN; ++k) {
        float m  = clo;
        int   ml = lane;
#pragma unroll
        for (int off = 16; off; off >>= 1) {
            float om = __shfl_xor_sync(FULL, m, off);
            int   ol = __shfl_xor_sync(FULL, ml, off);
            if (om < m || (om == m && ol < ml)) { m = om; ml = ol; }
        }
        int wi = __shfl_sync(FULL, ilo, ml);
        float dist = sqrtf(fmaxf(m, 0.0f));
        float wgt  = 1.0f / (dist + 1e-6f);
        wk[k] = wgt; bk[k] = wi; wsum += wgt;
        if (lane == ml) { clo = chi; ilo = ihi; chi = BIGF; }
    }

    float acc = 0.f;
#pragma unroll
    for (int k = 0; k < KNN; ++k)
        acc += wk[k] * aux[bk[k] * DAUX + lane];
    out[gw * DAUX + lane] = acc / wsum;
}

// ---------------------------------------------------------------------------
extern "C" void kernel_launch(void* const* d_in, const int* in_sizes, int n_in,
                              void* d_out, int out_size) {
    const float* q   = (const float*)d_in[0];   // embedding_features [4096,32]
    const float* db  = (const float*)d_in[1];   // db_embedding      [65536,32]
    const float* aux = (const float*)d_in[2];   // auxiliary_features[65536,32]
    float* out = (float*)d_out;                 // [4096,32]

    prep_hs<<<NDB / 32, 256>>>(db);
    prep_bf<<<NSLAB * 64 / 256, 256>>>(db);
    knn_mma<<<(NQ / QPC) * NSPLIT, 256>>>(q);
    merge_kernel<<<NQ / 8, 256>>>(q, db, aux, out);
}

// round 16
// speedup vs baseline: 2.7130x; 1.0436x over previous
#include <cuda_runtime.h>
#include <cuda_fp16.h>
#include <cstdint>

#define NQ      4096
#define NDB     65536
#define DIM     32
#define DAUX    32
#define KNN     5
#define NSLAB   (NDB / 32)         // 2048 32-point slabs
#define NSPLIT  4                  // db quarters per query tile
#define QPC     64                 // queries per CTA (4 m-tiles)
#define NS      (NSLAB / NSPLIT / 2)  // 256 slabs per warp (eighth of db)
#define NLIST   (NSPLIT * 2)       // 8 candidate lists per query
#define BIGF    3.0e38f

// ---------------- global scratch ----------------
// g_Bf: fp16 hi frag-packed db. Per 32-pt slab s: 128 uint4 =
//   [ntile j=0..3][lane 0..31]; lane uint4 = {ks0.b0, ks0.b1, ks1.b0, ks1.b1}
//   for point p = s*32 + j*8 + (lane>>2), k per m16n8k16 B layout.
__device__ uint4 g_Bf[NSLAB * 128];           // 4 MB
__device__ float g_hs[NDB];                   // 0.5*||db||^2
__device__ int   g_ci[NQ * NLIST * KNN];      // candidate indices

// ---------------- helpers ----------------
__device__ __forceinline__ uint32_t h2u(__half a, __half b) {
    __half2 h = __halves2half2(a, b);
    return *(uint32_t*)&h;
}
__device__ __forceinline__ void mma16(float* c, const uint32_t* a,
                                      uint32_t b0, uint32_t b1) {
    asm("mma.sync.aligned.m16n8k16.row.col.f32.f16.f16.f32 "
        "{%0,%1,%2,%3}, {%4,%5,%6,%7}, {%8,%9}, {%0,%1,%2,%3};"
        : "+f"(c[0]), "+f"(c[1]), "+f"(c[2]), "+f"(c[3])
        : "r"(a[0]), "r"(a[1]), "r"(a[2]), "r"(a[3]), "r"(b0), "r"(b1));
}
__device__ __forceinline__ void topk_ins(float* ts, int* ti, float s, int pi) {
    if (s < ts[4]) {
        ts[4] = s; ti[4] = pi;
        if (ts[4] < ts[3]) { float f = ts[3]; ts[3] = ts[4]; ts[4] = f; int i = ti[3]; ti[3] = ti[4]; ti[4] = i; }
        if (ts[3] < ts[2]) { float f = ts[2]; ts[2] = ts[3]; ts[3] = f; int i = ti[2]; ti[2] = ti[3]; ti[3] = i; }
        if (ts[2] < ts[1]) { float f = ts[1]; ts[1] = ts[2]; ts[2] = f; int i = ti[1]; ti[1] = ti[2]; ti[2] = i; }
        if (ts[1] < ts[0]) { float f = ts[0]; ts[0] = ts[1]; ts[1] = f; int i = ti[0]; ti[0] = ti[1]; ti[1] = i; }
    }
}

// ---------------------------------------------------------------------------
// prep_hs: 0.5*||db||^2 per point.
// ---------------------------------------------------------------------------
__global__ void prep_hs(const float* __restrict__ db) {
    const unsigned FULL = 0xffffffffu;
    const int p = blockIdx.x * 32 + (threadIdx.x >> 3);
    const int j = threadIdx.x & 7;
    float4 v = *(const float4*)(db + p * DIM + j * 4);
    float s = v.x * v.x + v.y * v.y + v.z * v.z + v.w * v.w;
    s += __shfl_xor_sync(FULL, s, 4, 8);
    s += __shfl_xor_sync(FULL, s, 2, 8);
    s += __shfl_xor_sync(FULL, s, 1, 8);
    if (j == 0) g_hs[p] = 0.5f * s;
}

// ---------------------------------------------------------------------------
// prep_bf: fp16 hi frag-packed db. One thread per (slab, ntile, lane).
// ---------------------------------------------------------------------------
__global__ void prep_bf(const float* __restrict__ db) {
    const int gid  = blockIdx.x * 256 + threadIdx.x;   // 0 .. NSLAB*128-1
    const int s    = gid >> 7;
    const int r    = gid & 127;
    const int j    = r >> 5;
    const int lane = r & 31;
    const int tig  = lane & 3;
    const int p    = s * 32 + j * 8 + (lane >> 2);

    const float* src = db + p * DIM;
    __half hi[8];
#pragma unroll
    for (int e = 0; e < 8; ++e) {
        // k-order: {2t,2t+1, 2t+8,2t+9, 2t+16,2t+17, 2t+24,2t+25}
        int k = 2 * tig + (e & 1) + 8 * (e >> 1);
        hi[e] = __float2half_rn(src[k]);
    }
    uint4 uh;
    uh.x = h2u(hi[0], hi[1]); uh.y = h2u(hi[2], hi[3]);
    uh.z = h2u(hi[4], hi[5]); uh.w = h2u(hi[6], hi[7]);
    g_Bf[s * 128 + j * 32 + lane] = uh;
}

// ---------------------------------------------------------------------------
// main: 256 CTAs (64 q-tiles x 4 db-splits), 256 threads, 2 CTAs/SM.
// hi-only fp16 scoring, 32-pt slabs: 8 MMAs in 4 depth-2 chains; per-list
// min-tree early-out so the branchy top-k path runs on <10% of iterations.
// ---------------------------------------------------------------------------
__global__ void __launch_bounds__(256, 2)
knn_mma(const float* __restrict__ q) {
    const unsigned FULL = 0xffffffffu;
    const int tid  = threadIdx.x;
    const int lane = tid & 31;
    const int tig  = lane & 3;
    const int wid  = tid >> 5;
    const int mi   = wid & 3;              // m-tile within CTA (16 queries)
    const int ph   = wid >> 2;             // p-half within this CTA's db split
    const int qb   = blockIdx.x >> 2;      // 0..63 query tile
    const int sp   = blockIdx.x & 3;       // db split (quarter)
    const int w8   = sp * 2 + ph;          // candidate-list slot 0..7

    const int r0 = qb * QPC + mi * 16 + (lane >> 2);  // this thread's 2 queries
    const int r1 = r0 + 8;

    // ---- A fragments (hi only): Ahi[ks][a0..a3] ----
    uint32_t Ahi[2][4];
    {
        const float* q0 = q + r0 * DIM;
        const float* q1 = q + r1 * DIM;
#pragma unroll
        for (int ks = 0; ks < 2; ++ks) {
            int kb = 16 * ks + 2 * tig;
            Ahi[ks][0] = h2u(__float2half_rn(q0[kb]),     __float2half_rn(q0[kb + 1]));
            Ahi[ks][1] = h2u(__float2half_rn(q1[kb]),     __float2half_rn(q1[kb + 1]));
            Ahi[ks][2] = h2u(__float2half_rn(q0[kb + 8]), __float2half_rn(q0[kb + 9]));
            Ahi[ks][3] = h2u(__float2half_rn(q1[kb + 8]), __float2half_rn(q1[kb + 9]));
        }
    }

    float tsA[KNN], tsB[KNN];
    int   tiA[KNN], tiB[KNN];
#pragma unroll
    for (int k = 0; k < KNN; ++k) {
        tsA[k] = BIGF; tiA[k] = 0;
        tsB[k] = BIGF; tiB[k] = 0;
    }

    // ---- stream 32-point slabs ----
    const int sg0 = sp * (NSLAB / NSPLIT) + ph * NS;   // first slab
    const uint4* bp = g_Bf + (size_t)sg0 * 128;
    const float* hp = g_hs + sg0 * 32 + 2 * tig;

    // prefetch slab 0 (B frags only; hs stays on the L1 path)
    uint4 nb0 = bp[lane],      nb1 = bp[32 + lane];
    uint4 nb2 = bp[64 + lane], nb3 = bp[96 + lane];

    for (int t = 0; t < NS; ++t) {
        uint4 b0 = nb0, b1 = nb1, b2 = nb2, b3 = nb3;
        if (t + 1 < NS) {
            bp += 128;
            nb0 = bp[lane];      nb1 = bp[32 + lane];
            nb2 = bp[64 + lane]; nb3 = bp[96 + lane];
        }

        // four independent chains, depth 2 (one per n-tile)
        float c0[4] = {0.f, 0.f, 0.f, 0.f};
        float c1[4] = {0.f, 0.f, 0.f, 0.f};
        float c2[4] = {0.f, 0.f, 0.f, 0.f};
        float c3[4] = {0.f, 0.f, 0.f, 0.f};
        mma16(c0, Ahi[0], b0.x, b0.y);
        mma16(c1, Ahi[0], b1.x, b1.y);
        mma16(c2, Ahi[0], b2.x, b2.y);
        mma16(c3, Ahi[0], b3.x, b3.y);
        mma16(c0, Ahi[1], b0.z, b0.w);
        mma16(c1, Ahi[1], b1.z, b1.w);
        mma16(c2, Ahi[1], b2.z, b2.w);
        mma16(c3, Ahi[1], b3.z, b3.w);

        const float* hb = hp + (size_t)t * 32;
        float2 h0 = *(const float2*)hb;
        float2 h1 = *(const float2*)(hb + 8);
        float2 h2 = *(const float2*)(hb + 16);
        float2 h3 = *(const float2*)(hb + 24);

        // approx scores (selection only)
        float sA0 = h0.x - c0[0], sA1 = h0.y - c0[1];
        float sA2 = h1.x - c1[0], sA3 = h1.y - c1[1];
        float sA4 = h2.x - c2[0], sA5 = h2.y - c2[1];
        float sA6 = h3.x - c3[0], sA7 = h3.y - c3[1];
        float sB0 = h0.x - c0[2], sB1 = h0.y - c0[3];
        float sB2 = h1.x - c1[2], sB3 = h1.y - c1[3];
        float sB4 = h2.x - c2[2], sB5 = h2.y - c2[3];
        float sB6 = h3.x - c3[2], sB7 = h3.y - c3[3];

        const int p0 = (sg0 + t) * 32 + 2 * tig;

        // min-tree early-out per list
        float mA = fminf(fminf(fminf(sA0, sA1), fminf(sA2, sA3)),
                         fminf(fminf(sA4, sA5), fminf(sA6, sA7)));
        if (mA < tsA[4]) {
            topk_ins(tsA, tiA, sA0, p0);      topk_ins(tsA, tiA, sA1, p0 + 1);
            topk_ins(tsA, tiA, sA2, p0 + 8);  topk_ins(tsA, tiA, sA3, p0 + 9);
            topk_ins(tsA, tiA, sA4, p0 + 16); topk_ins(tsA, tiA, sA5, p0 + 17);
            topk_ins(tsA, tiA, sA6, p0 + 24); topk_ins(tsA, tiA, sA7, p0 + 25);
        }
        float mB = fminf(fminf(fminf(sB0, sB1), fminf(sB2, sB3)),
                         fminf(fminf(sB4, sB5), fminf(sB6, sB7)));
        if (mB < tsB[4]) {
            topk_ins(tsB, tiB, sB0, p0);      topk_ins(tsB, tiB, sB1, p0 + 1);
            topk_ins(tsB, tiB, sB2, p0 + 8);  topk_ins(tsB, tiB, sB3, p0 + 9);
            topk_ins(tsB, tiB, sB4, p0 + 16); topk_ins(tsB, tiB, sB5, p0 + 17);
            topk_ins(tsB, tiB, sB6, p0 + 24); topk_ins(tsB, tiB, sB7, p0 + 25);
        }

        if ((t & 15) == 15) __syncthreads();    // keep warps in L1 window
    }

    // ---- quad-merge (4 lanes share each query); write 5 indices per list ----
#pragma unroll
    for (int l = 0; l < 2; ++l) {
        float c0_ = l ? tsB[0] : tsA[0], c1_ = l ? tsB[1] : tsA[1],
              c2_ = l ? tsB[2] : tsA[2], c3_ = l ? tsB[3] : tsA[3],
              c4_ = l ? tsB[4] : tsA[4];
        int   j0 = l ? tiB[0] : tiA[0], j1 = l ? tiB[1] : tiA[1],
              j2 = l ? tiB[2] : tiA[2], j3 = l ? tiB[3] : tiA[3],
              j4 = l ? tiB[4] : tiA[4];
        const int qi = l ? r1 : r0;

#pragma unroll
        for (int k = 0; k < KNN; ++k) {
            float m  = c0_;
            int   ml = lane;
            float om = __shfl_xor_sync(FULL, m, 1, 4);
            int   ol = __shfl_xor_sync(FULL, ml, 1, 4);
            if (om < m || (om == m && ol < ml)) { m = om; ml = ol; }
            om = __shfl_xor_sync(FULL, m, 2, 4);
            ol = __shfl_xor_sync(FULL, ml, 2, 4);
            if (om < m || (om == m && ol < ml)) { m = om; ml = ol; }
            int wi = __shfl_sync(FULL, j0, ml & 3, 4);
            if (lane == ml) {
                c0_ = c1_; c1_ = c2_; c2_ = c3_; c3_ = c4_; c4_ = BIGF;
                j0 = j1; j1 = j2; j2 = j3; j3 = j4;
            }
            if (tig == 0)
                g_ci[(qi * NLIST + w8) * KNN + k] = wi;
        }
    }
}

// ---------------------------------------------------------------------------
// merge: one warp per query; 40 candidate indices -> EXACT fp32 distances
// -> top-5 -> weighted aux gather
// ---------------------------------------------------------------------------
__device__ __forceinline__ float dist2(const float* __restrict__ q,
                                       const float* __restrict__ db,
                                       int gw, int pi) {
    float s = 0.f;
#pragma unroll
    for (int d = 0; d < 8; ++d) {
        float4 a = *(const float4*)(q + gw * DIM + d * 4);
        float4 b = *(const float4*)(db + pi * DIM + d * 4);
        float dx = a.x - b.x, dy = a.y - b.y, dz = a.z - b.z, dw = a.w - b.w;
        s += dx * dx + dy * dy + dz * dz + dw * dw;
    }
    return s;
}

__global__ void merge_kernel(const float* __restrict__ q,
                             const float* __restrict__ db,
                             const float* __restrict__ aux,
                             float* __restrict__ out) {
    const unsigned FULL = 0xffffffffu;
    const int gw   = (blockIdx.x * blockDim.x + threadIdx.x) >> 5;
    const int lane = threadIdx.x & 31;
    if (gw >= NQ) return;

    const int NC = NLIST * KNN;                 // 40
    int   ilo = g_ci[gw * NC + lane];
    int   ihi = (lane < NC - 32) ? g_ci[gw * NC + 32 + lane] : 0;

    // exact squared distances (disjoint db ranges -> no duplicate indices)
    float clo = dist2(q, db, gw, ilo);
    float chi = (lane < NC - 32) ? dist2(q, db, gw, ihi) : BIGF;
    if (chi < clo) { float f = clo; clo = chi; chi = f; int i = ilo; ilo = ihi; ihi = i; }

    float wk[KNN]; int bk[KNN];
    float wsum = 0.f;
#pragma unroll
    for (int k = 0; k < KNN; ++k) {
        float m  = clo;
        int   ml = lane;
#pragma unroll
        for (int off = 16; off; off >>= 1) {
            float om = __shfl_xor_sync(FULL, m, off);
            int   ol = __shfl_xor_sync(FULL, ml, off);
            if (om < m || (om == m && ol < ml)) { m = om; ml = ol; }
        }
        int wi = __shfl_sync(FULL, ilo, ml);
        float dist = sqrtf(fmaxf(m, 0.0f));
        float wgt  = 1.0f / (dist + 1e-6f);
        wk[k] = wgt; bk[k] = wi; wsum += wgt;
        if (lane == ml) { clo = chi; ilo = ihi; chi = BIGF; }
    }

    float acc = 0.f;
#pragma unroll
    for (int k = 0; k < KNN; ++k)
        acc += wk[k] * aux[bk[k] * DAUX + lane];
    out[gw * DAUX + lane] = acc / wsum;
}

// ---------------------------------------------------------------------------
extern "C" void kernel_launch(void* const* d_in, const int* in_sizes, int n_in,
                              void* d_out, int out_size) {
    const float* q   = (const float*)d_in[0];   // embedding_features [4096,32]
    const float* db  = (const float*)d_in[1];   // db_embedding      [65536,32]
    const float* aux = (const float*)d_in[2];   // auxiliary_features[65536,32]
    float* out = (float*)d_out;                 // [4096,32]

    prep_hs<<<NDB / 32, 256>>>(db);
    prep_bf<<<NSLAB * 128 / 256, 256>>>(db);
    knn_mma<<<(NQ / QPC) * NSPLIT, 256>>>(q);
    merge_kernel<<<NQ / 8, 256>>>(q, db, aux, out);
}